// round 1
// baseline (speedup 1.0000x reference)
#include <cuda_runtime.h>
#include <math.h>

#define NTOK 4096
#define WID  512
#define FTOT 1024
#define SPECTRAL_SCALE 0.8f
#define ES_BETA 6.0f
#define TAU 0.001f
#define RHO 0.25f
#define LN_EPS 1e-5f
#define EPS_RMS 1e-8f

// Scratch (no cudaMalloc allowed)
__device__ float g_xn[NTOK * WID];     // layernormed x
__device__ float g_spec[NTOK * WID];   // RHO * h_spec / rms
__device__ float g_fnz[WID * FTOT];    // per-width nonzero freqs
__device__ float g_tnz[WID * FTOT];    // per-width nonzero thresholded weights
__device__ int   g_cnt[WID];           // per-width nonzero count
__device__ int   g_denom_bits;         // max|f| as float bits (>=0 so int-compare works)

// ---------------------------------------------------------------- reset
__global__ void k_reset() {
    int i = blockIdx.x * blockDim.x + threadIdx.x;
    if (i < WID) g_cnt[i] = 0;
    if (i == 0)  g_denom_bits = 0;
}

// ---------------------------------------------------------------- max|freq*scale|
__global__ void k_maxabs(const float* __restrict__ freq) {
    float m = 0.f;
    for (int idx = blockIdx.x * blockDim.x + threadIdx.x; idx < FTOT * WID;
         idx += gridDim.x * blockDim.x)
        m = fmaxf(m, fabsf(freq[idx]) * SPECTRAL_SCALE);
    #pragma unroll
    for (int o = 16; o; o >>= 1) m = fmaxf(m, __shfl_xor_sync(0xffffffffu, m, o));
    __shared__ float s[32];
    int lane = threadIdx.x & 31, wid = threadIdx.x >> 5;
    if (lane == 0) s[wid] = m;
    __syncthreads();
    if (wid == 0) {
        m = (lane < (blockDim.x >> 5)) ? s[lane] : 0.f;
        #pragma unroll
        for (int o = 16; o; o >>= 1) m = fmaxf(m, __shfl_xor_sync(0xffffffffu, m, o));
        if (lane == 0) atomicMax(&g_denom_bits, __float_as_int(m));
    }
}

// ---------------------------------------------------------------- thresholded weights -> compact lists
__global__ void k_thr(const float* __restrict__ freq, const float* __restrict__ alpha,
                      const float* __restrict__ gate) {
    int i = blockIdx.x * blockDim.x + threadIdx.x;
    if (i >= FTOT * WID) return;
    float denom = __int_as_float(g_denom_bits);
    float f = freq[i] * SPECTRAL_SCALE;
    float win;
    if (denom < 1e-8f) {
        win = 1.f;
    } else {
        float r = f / denom;
        win = expf(-ES_BETA * r * r);
    }
    float raw = alpha[i] * gate[i];
    float mag = fabsf(raw) - TAU;
    if (mag > 0.f) {
        float t = copysignf(mag, raw) * win;
        if (t != 0.f) {
            int w = i & (WID - 1);
            int pos = atomicAdd(&g_cnt[w], 1);
            g_fnz[w * FTOT + pos] = f;
            g_tnz[w * FTOT + pos] = t;
        }
    }
}

// ---------------------------------------------------------------- LayerNorm (1 block / token)
__global__ void __launch_bounds__(128) k_ln(const float* __restrict__ x,
                                            const float* __restrict__ gamma,
                                            const float* __restrict__ beta) {
    int n = blockIdx.x;
    int t = threadIdx.x;
    const float4* x4 = (const float4*)(x + (size_t)n * WID);
    float4 v = x4[t];
    float s = v.x + v.y + v.z + v.w;
    float q = v.x * v.x + v.y * v.y + v.z * v.z + v.w * v.w;
    #pragma unroll
    for (int o = 16; o; o >>= 1) {
        s += __shfl_xor_sync(0xffffffffu, s, o);
        q += __shfl_xor_sync(0xffffffffu, q, o);
    }
    __shared__ float ss[4], sq[4];
    int lane = t & 31, wid = t >> 5;
    if (lane == 0) { ss[wid] = s; sq[wid] = q; }
    __syncthreads();
    s = ss[0] + ss[1] + ss[2] + ss[3];
    q = sq[0] + sq[1] + sq[2] + sq[3];
    float mu  = s * (1.f / WID);
    float var = q * (1.f / WID) - mu * mu;
    float inv = rsqrtf(var + LN_EPS);
    float4 g = ((const float4*)gamma)[t];
    float4 b = ((const float4*)beta)[t];
    float4 o;
    o.x = (v.x - mu) * inv * g.x + b.x;
    o.y = (v.y - mu) * inv * g.y + b.y;
    o.z = (v.z - mu) * inv * g.z + b.z;
    o.w = (v.w - mu) * inv * g.w + b.w;
    ((float4*)(g_xn + (size_t)n * WID))[t] = o;
}

// ---------------------------------------------------------------- spectral branch (1 block / token)
__global__ void __launch_bounds__(512) k_spec() {
    int n = blockIdx.x, w = threadIdx.x;
    float xn = g_xn[(size_t)n * WID + w];
    int cnt = g_cnt[w];
    const float* fp = g_fnz + w * FTOT;
    const float* tp = g_tnz + w * FTOT;
    float s = 0.f;
    for (int i = 0; i < cnt; ++i)
        s += __sinf(xn * fp[i]) * tp[i];
    float q = s * s;
    #pragma unroll
    for (int o = 16; o; o >>= 1) q += __shfl_xor_sync(0xffffffffu, q, o);
    __shared__ float sq[16];
    int lane = w & 31, wid = w >> 5;
    if (lane == 0) sq[wid] = q;
    __syncthreads();
    float tot = 0.f;
    #pragma unroll
    for (int i = 0; i < 16; ++i) tot += sq[i];
    float rms = sqrtf(tot * (1.f / WID) + EPS_RMS);
    g_spec[(size_t)n * WID + w] = RHO * s / rms;
}

// ---------------------------------------------------------------- GEMM + bias + GELU + spec add
#define BM 128
#define BN 128
#define BK 16
__global__ void __launch_bounds__(256) k_gemm(const float* __restrict__ Wm,
                                              const float* __restrict__ bias,
                                              float* __restrict__ out) {
    __shared__ float As[BK][BM + 4];
    __shared__ float Bs[BK][BN + 4];
    const float* A = g_xn;
    int bm = blockIdx.y * BM;
    int bn = blockIdx.x * BN;
    int tid = threadIdx.x;
    int tx = tid & 15, ty = tid >> 4;
    float acc[8][8] = {};
    int lr = tid >> 2;          // 0..63
    int lc = (tid & 3) << 2;    // 0,4,8,12

    for (int k0 = 0; k0 < WID; k0 += BK) {
        #pragma unroll
        for (int it = 0; it < 2; ++it) {
            int r = lr + it * 64;
            float4 a = *(const float4*)(A  + (size_t)(bm + r) * WID + k0 + lc);
            As[lc + 0][r] = a.x; As[lc + 1][r] = a.y;
            As[lc + 2][r] = a.z; As[lc + 3][r] = a.w;
            float4 b = *(const float4*)(Wm + (size_t)(bn + r) * WID + k0 + lc);
            Bs[lc + 0][r] = b.x; Bs[lc + 1][r] = b.y;
            Bs[lc + 2][r] = b.z; Bs[lc + 3][r] = b.w;
        }
        __syncthreads();
        #pragma unroll
        for (int kk = 0; kk < BK; ++kk) {
            float4 a0 = *(const float4*)&As[kk][ty * 8];
            float4 a1 = *(const float4*)&As[kk][ty * 8 + 4];
            float4 b0 = *(const float4*)&Bs[kk][tx * 8];
            float4 b1 = *(const float4*)&Bs[kk][tx * 8 + 4];
            float af[8] = {a0.x, a0.y, a0.z, a0.w, a1.x, a1.y, a1.z, a1.w};
            float bf[8] = {b0.x, b0.y, b0.z, b0.w, b1.x, b1.y, b1.z, b1.w};
            #pragma unroll
            for (int i = 0; i < 8; ++i)
                #pragma unroll
                for (int j = 0; j < 8; ++j)
                    acc[i][j] = fmaf(af[i], bf[j], acc[i][j]);
        }
        __syncthreads();
    }

    #pragma unroll
    for (int i = 0; i < 8; ++i) {
        int row = bm + ty * 8 + i;
        #pragma unroll
        for (int j = 0; j < 8; j += 4) {
            int col = bn + tx * 8 + j;
            float4 o;
            float* po = &o.x;
            #pragma unroll
            for (int u = 0; u < 4; ++u) {
                float v = acc[i][j + u] + bias[col + u];
                float gl = 0.5f * v * (1.f + erff(v * 0.70710678118654752f));
                po[u] = gl + g_spec[(size_t)row * WID + col + u];
            }
            *(float4*)(out + (size_t)row * WID + col) = o;
        }
    }
}

// ---------------------------------------------------------------- launch
extern "C" void kernel_launch(void* const* d_in, const int* in_sizes, int n_in,
                              void* d_out, int out_size) {
    const float* x       = (const float*)d_in[0];
    const float* freq    = (const float*)d_in[1];
    const float* alpha   = (const float*)d_in[2];
    const float* gate    = (const float*)d_in[3];
    const float* ln_g    = (const float*)d_in[4];
    const float* ln_b    = (const float*)d_in[5];
    const float* w_loc   = (const float*)d_in[6];
    const float* b_loc   = (const float*)d_in[7];
    float* out = (float*)d_out;

    k_reset<<<1, 512>>>();
    k_maxabs<<<512, 256>>>(freq);
    k_thr<<<(FTOT * WID) / 256, 256>>>(freq, alpha, gate);
    k_ln<<<NTOK, 128>>>(x, ln_g, ln_b);
    k_spec<<<NTOK, 512>>>();
    k_gemm<<<dim3(WID / BN, NTOK / BM), 256>>>(w_loc, b_loc, out);
}

// round 3
// speedup vs baseline: 1.4751x; 1.4751x over previous
#include <cuda_runtime.h>
#include <cuda_bf16.h>
#include <cstdint>
#include <math.h>

#define NTOK 4096
#define WID  512
#define FTOT 1024
#define SPECTRAL_SCALE 0.8f
#define ES_BETA 6.0f
#define TAU 0.001f
#define RHO 0.25f
#define LN_EPS 1e-5f
#define EPS_RMS 1e-8f

// ----- GEMM tiling -----
#define TM 128
#define TN 128
#define KC 64             // bf16 K elems per chunk
#define NCH 24            // 3 passes x 8 chunks (hi*hi, hi*lo, lo*hi)
#define STAGES 3
#define ROWB 144          // padded row bytes: 72 bf16 (conflict-free ldmatrix)
#define ATILEB (TM * ROWB)        // 18432
#define STGB  (2 * ATILEB)        // A + B per stage = 36864
#define SMEM_TOTAL (STAGES * STGB)  // 110592

// Scratch (no cudaMalloc allowed)
__device__ __nv_bfloat16 g_ahi[NTOK * WID];
__device__ __nv_bfloat16 g_alo[NTOK * WID];
__device__ __nv_bfloat16 g_whi[WID * WID];
__device__ __nv_bfloat16 g_wlo[WID * WID];
__device__ float g_spec[NTOK * WID];
__device__ float g_fnz[WID * FTOT];
__device__ float g_tnz[WID * FTOT];
__device__ int   g_cnt[WID];
__device__ int   g_denom_bits;

// ============================ PTX helpers ============================
__device__ __forceinline__ uint32_t smem_u32(const void* p) {
    uint32_t a;
    asm("{ .reg .u64 t; cvta.to.shared.u64 t, %1; cvt.u32.u64 %0, t; }" : "=r"(a) : "l"(p));
    return a;
}
__device__ __forceinline__ void cp_async16(uint32_t saddr, const void* gaddr) {
    asm volatile("cp.async.cg.shared.global [%0], [%1], 16;" :: "r"(saddr), "l"(gaddr));
}
#define CP_COMMIT() asm volatile("cp.async.commit_group;" ::: "memory")

__device__ __forceinline__ void ldsm_x4(uint32_t* r, uint32_t a) {
    asm volatile("ldmatrix.sync.aligned.m8n8.x4.shared.b16 {%0,%1,%2,%3}, [%4];"
                 : "=r"(r[0]), "=r"(r[1]), "=r"(r[2]), "=r"(r[3]) : "r"(a));
}
__device__ __forceinline__ void mma16816(float* d, const uint32_t* a, uint32_t b0, uint32_t b1) {
    asm volatile(
        "mma.sync.aligned.m16n8k16.row.col.f32.bf16.bf16.f32 "
        "{%0,%1,%2,%3}, {%4,%5,%6,%7}, {%8,%9}, {%0,%1,%2,%3};"
        : "+f"(d[0]), "+f"(d[1]), "+f"(d[2]), "+f"(d[3])
        : "r"(a[0]), "r"(a[1]), "r"(a[2]), "r"(a[3]), "r"(b0), "r"(b1));
}

// ============================ small prep kernels ============================
__global__ void k_reset() {
    int i = blockIdx.x * blockDim.x + threadIdx.x;
    if (i < WID) g_cnt[i] = 0;
    if (i == 0)  g_denom_bits = 0;
}

__global__ void k_maxabs(const float* __restrict__ freq) {
    float m = 0.f;
    for (int idx = blockIdx.x * blockDim.x + threadIdx.x; idx < FTOT * WID;
         idx += gridDim.x * blockDim.x)
        m = fmaxf(m, fabsf(freq[idx]) * SPECTRAL_SCALE);
    #pragma unroll
    for (int o = 16; o; o >>= 1) m = fmaxf(m, __shfl_xor_sync(0xffffffffu, m, o));
    __shared__ float s[32];
    int lane = threadIdx.x & 31, wd = threadIdx.x >> 5;
    if (lane == 0) s[wd] = m;
    __syncthreads();
    if (wd == 0) {
        m = (lane < (blockDim.x >> 5)) ? s[lane] : 0.f;
        #pragma unroll
        for (int o = 16; o; o >>= 1) m = fmaxf(m, __shfl_xor_sync(0xffffffffu, m, o));
        if (lane == 0) atomicMax(&g_denom_bits, __float_as_int(m));
    }
}

__global__ void k_thr(const float* __restrict__ freq, const float* __restrict__ alpha,
                      const float* __restrict__ gate) {
    int i = blockIdx.x * blockDim.x + threadIdx.x;
    if (i >= FTOT * WID) return;
    float denom = __int_as_float(g_denom_bits);
    float f = freq[i] * SPECTRAL_SCALE;
    float win;
    if (denom < 1e-8f) win = 1.f;
    else { float r = f / denom; win = expf(-ES_BETA * r * r); }
    float raw = alpha[i] * gate[i];
    float mag = fabsf(raw) - TAU;
    if (mag > 0.f) {
        float t = copysignf(mag, raw) * win;
        if (t != 0.f) {
            int w = i & (WID - 1);
            int pos = atomicAdd(&g_cnt[w], 1);
            g_fnz[w * FTOT + pos] = f;
            g_tnz[w * FTOT + pos] = t;
        }
    }
}

__global__ void k_wprep(const float* __restrict__ w) {
    int i = blockIdx.x * blockDim.x + threadIdx.x;
    if (i >= WID * WID) return;
    float v = w[i];
    __nv_bfloat16 hi = __float2bfloat16(v);
    g_whi[i] = hi;
    g_wlo[i] = __float2bfloat16(v - __bfloat162float(hi));
}

// ---- LayerNorm: warp per row, fused bf16 hi/lo split ----
__global__ void __launch_bounds__(256) k_ln(const float* __restrict__ x,
                                            const float* __restrict__ gamma,
                                            const float* __restrict__ beta) {
    int lane = threadIdx.x & 31;
    int row = blockIdx.x * 8 + (threadIdx.x >> 5);
    const float4* xr = (const float4*)(x + (size_t)row * WID);
    float4 v[4];
    float s = 0.f, q = 0.f;
    #pragma unroll
    for (int i = 0; i < 4; ++i) {
        v[i] = xr[lane + 32 * i];
        s += v[i].x + v[i].y + v[i].z + v[i].w;
        q += v[i].x * v[i].x + v[i].y * v[i].y + v[i].z * v[i].z + v[i].w * v[i].w;
    }
    #pragma unroll
    for (int o = 16; o; o >>= 1) {
        s += __shfl_xor_sync(0xffffffffu, s, o);
        q += __shfl_xor_sync(0xffffffffu, q, o);
    }
    float mu = s * (1.f / WID);
    float inv = rsqrtf(q * (1.f / WID) - mu * mu + LN_EPS);
    #pragma unroll
    for (int i = 0; i < 4; ++i) {
        int cb = (lane + 32 * i) * 4;
        float4 g = ((const float4*)gamma)[lane + 32 * i];
        float4 b = ((const float4*)beta)[lane + 32 * i];
        float o0 = (v[i].x - mu) * inv * g.x + b.x;
        float o1 = (v[i].y - mu) * inv * g.y + b.y;
        float o2 = (v[i].z - mu) * inv * g.z + b.z;
        float o3 = (v[i].w - mu) * inv * g.w + b.w;
        __nv_bfloat16 h0 = __float2bfloat16(o0), h1 = __float2bfloat16(o1);
        __nv_bfloat16 h2 = __float2bfloat16(o2), h3 = __float2bfloat16(o3);
        __nv_bfloat162 hp0(h0, h1), hp1(h2, h3);
        *(uint2*)&g_ahi[(size_t)row * WID + cb] =
            make_uint2(*(uint32_t*)&hp0, *(uint32_t*)&hp1);
        __nv_bfloat162 lp0(__float2bfloat16(o0 - __bfloat162float(h0)),
                           __float2bfloat16(o1 - __bfloat162float(h1)));
        __nv_bfloat162 lp1(__float2bfloat16(o2 - __bfloat162float(h2)),
                           __float2bfloat16(o3 - __bfloat162float(h3)));
        *(uint2*)&g_alo[(size_t)row * WID + cb] =
            make_uint2(*(uint32_t*)&lp0, *(uint32_t*)&lp1);
    }
}

// ---- spectral branch ----
__global__ void __launch_bounds__(512) k_spec() {
    int n = blockIdx.x, w = threadIdx.x;
    size_t off = (size_t)n * WID + w;
    float xn = __bfloat162float(g_ahi[off]) + __bfloat162float(g_alo[off]);
    int cnt = g_cnt[w];
    const float* fp = g_fnz + w * FTOT;
    const float* tp = g_tnz + w * FTOT;
    float s = 0.f;
    for (int i = 0; i < cnt; ++i)
        s += __sinf(xn * fp[i]) * tp[i];
    float q = s * s;
    #pragma unroll
    for (int o = 16; o; o >>= 1) q += __shfl_xor_sync(0xffffffffu, q, o);
    __shared__ float sq[16];
    int lane = w & 31, wd = w >> 5;
    if (lane == 0) sq[wd] = q;
    __syncthreads();
    float tot = 0.f;
    #pragma unroll
    for (int i = 0; i < 16; ++i) tot += sq[i];
    float rms = sqrtf(tot * (1.f / WID) + EPS_RMS);
    g_spec[off] = RHO * s / rms;
}

// ============================ HMMA GEMM ============================
__global__ void __launch_bounds__(256, 1)
k_mma(const float* __restrict__ bias, float* __restrict__ out) {
    extern __shared__ char smem[];
    uint32_t sb = smem_u32(smem);
    int tid = threadIdx.x;
    int wid = tid >> 5, lane = tid & 31;
    int warp_m = wid & 1;        // 2 warps over M (64 rows each)
    int warp_n = wid >> 1;       // 4 warps over N (32 cols each)

    int bm = blockIdx.y * TM;
    int bn = blockIdx.x * TN;

    float acc[4][4][4];
    #pragma unroll
    for (int i = 0; i < 4; ++i)
        #pragma unroll
        for (int j = 0; j < 4; ++j)
            #pragma unroll
            for (int k = 0; k < 4; ++k) acc[i][j][k] = 0.f;

    // ---- chunk loader ----
    auto load_chunk = [&](int c, int stg) {
        const __nv_bfloat16* As = (c < 16) ? g_ahi : g_alo;
        const __nv_bfloat16* Bs = (c >= 8 && c < 16) ? g_wlo : g_whi;
        int kcol = (c & 7) * KC;
        uint32_t abase = sb + stg * STGB;
        #pragma unroll
        for (int it = 0; it < 4; ++it) {
            int idx = it * 256 + tid;     // 0..1023
            int row = idx >> 3;
            int c16 = idx & 7;
            uint32_t so = (uint32_t)(row * ROWB + c16 * 16);
            cp_async16(abase + so, As + (size_t)(bm + row) * WID + kcol + c16 * 8);
            cp_async16(abase + ATILEB + so, Bs + (size_t)(bn + row) * WID + kcol + c16 * 8);
        }
        CP_COMMIT();
    };

    load_chunk(0, 0);
    load_chunk(1, 1);

    for (int c = 0; c < NCH; ++c) {
        if (c < NCH - 1) asm volatile("cp.async.wait_group 1;" ::: "memory");
        else             asm volatile("cp.async.wait_group 0;" ::: "memory");
        __syncthreads();
        if (c + 2 < NCH) load_chunk(c + 2, (c + 2) % STAGES);

        int stg = c % STAGES;
        uint32_t a_base = sb + stg * STGB;
        uint32_t b_base = a_base + ATILEB;
        #pragma unroll
        for (int ks = 0; ks < 4; ++ks) {
            uint32_t af[4][4];
            #pragma unroll
            for (int mt = 0; mt < 4; ++mt) {
                uint32_t addr = a_base
                    + (uint32_t)((warp_m * 64 + mt * 16 + (lane & 15)) * ROWB
                                 + (ks * 16 + (lane >> 4) * 8) * 2);
                ldsm_x4(af[mt], addr);
            }
            uint32_t bf[2][4];
            #pragma unroll
            for (int bt = 0; bt < 2; ++bt) {
                int nrow = warp_n * 32 + bt * 16 + (lane & 7) + ((lane >> 4) << 3);
                uint32_t addr = b_base
                    + (uint32_t)(nrow * ROWB + (ks * 16 + ((lane >> 3) & 1) * 8) * 2);
                ldsm_x4(bf[bt], addr);
            }
            #pragma unroll
            for (int mt = 0; mt < 4; ++mt)
                #pragma unroll
                for (int nt = 0; nt < 4; ++nt)
                    mma16816(acc[mt][nt], af[mt], bf[nt >> 1][(nt & 1) * 2],
                             bf[nt >> 1][(nt & 1) * 2 + 1]);
        }
    }

    // ---- epilogue: bias + exact GELU + spectral add ----
    #pragma unroll
    for (int mt = 0; mt < 4; ++mt) {
        int r0 = bm + warp_m * 64 + mt * 16 + (lane >> 2);
        #pragma unroll
        for (int nt = 0; nt < 4; ++nt) {
            int c0 = bn + warp_n * 32 + nt * 8 + (lane & 3) * 2;
            float b0 = bias[c0], b1 = bias[c0 + 1];
            #pragma unroll
            for (int h = 0; h < 2; ++h) {
                int r = r0 + h * 8;
                float v0 = acc[mt][nt][h * 2 + 0] + b0;
                float v1 = acc[mt][nt][h * 2 + 1] + b1;
                float g0 = 0.5f * v0 * (1.f + erff(v0 * 0.70710678118654752f));
                float g1 = 0.5f * v1 * (1.f + erff(v1 * 0.70710678118654752f));
                float2 sp = *(const float2*)(g_spec + (size_t)r * WID + c0);
                float2 o = make_float2(g0 + sp.x, g1 + sp.y);
                *(float2*)(out + (size_t)r * WID + c0) = o;
            }
        }
    }
}

// ============================ launch ============================
extern "C" void kernel_launch(void* const* d_in, const int* in_sizes, int n_in,
                              void* d_out, int out_size) {
    const float* x     = (const float*)d_in[0];
    const float* freq  = (const float*)d_in[1];
    const float* alpha = (const float*)d_in[2];
    const float* gate  = (const float*)d_in[3];
    const float* ln_g  = (const float*)d_in[4];
    const float* ln_b  = (const float*)d_in[5];
    const float* w_loc = (const float*)d_in[6];
    const float* b_loc = (const float*)d_in[7];
    float* out = (float*)d_out;

    static bool attr_done = false;
    if (!attr_done) {
        cudaFuncSetAttribute(k_mma, cudaFuncAttributeMaxDynamicSharedMemorySize, SMEM_TOTAL);
        attr_done = true;
    }

    k_reset<<<1, 512>>>();
    k_maxabs<<<512, 256>>>(freq);
    k_thr<<<(FTOT * WID) / 256, 256>>>(freq, alpha, gate);
    k_wprep<<<(WID * WID) / 256, 256>>>(w_loc);
    k_ln<<<NTOK / 8, 256>>>(x, ln_g, ln_b);
    k_spec<<<NTOK, 512>>>();
    k_mma<<<dim3(WID / TN, NTOK / TM), 256, SMEM_TOTAL>>>(b_loc, out);
}

// round 6
// speedup vs baseline: 2.1374x; 1.4490x over previous
#include <cuda_runtime.h>
#include <cuda_bf16.h>
#include <cstdint>
#include <math.h>

#define NTOK 4096
#define WID  512
#define FTOT 1024
#define SPECTRAL_SCALE 0.8f
#define ES_BETA 6.0f
#define TAU 0.001f
#define RHO 0.25f
#define LN_EPS 1e-5f
#define EPS_RMS 1e-8f

// ----- GEMM tiling -----
#define TM 128
#define TN 128
#define KC 64             // bf16 K elems per outer chunk
#define NKCH 8            // 512 / 64
#define ROWB 144          // padded row bytes: 72 bf16 (conflict-free ldmatrix)
#define ATILEB (TM * ROWB)          // 18432
#define STGB  (4 * ATILEB)          // A_hi, A_lo, W_hi, W_lo = 73728
#define SMEM_TOTAL (2 * STGB)       // 147456 (double buffer)

// Scratch (no cudaMalloc allowed)
__device__ __nv_bfloat16 g_ahi[NTOK * WID];
__device__ __nv_bfloat16 g_alo[NTOK * WID];
__device__ __nv_bfloat16 g_whi[WID * WID];
__device__ __nv_bfloat16 g_wlo[WID * WID];
__device__ float g_spec[NTOK * WID];
__device__ float g_fnz[WID * FTOT];
__device__ float g_tnz[WID * FTOT];
__device__ int   g_cnt[WID];
__device__ float g_blockmax[512];

// ============================ PTX helpers ============================
__device__ __forceinline__ uint32_t smem_u32(const void* p) {
    uint32_t a;
    asm("{ .reg .u64 t; cvta.to.shared.u64 t, %1; cvt.u32.u64 %0, t; }" : "=r"(a) : "l"(p));
    return a;
}
__device__ __forceinline__ void cp_async16(uint32_t saddr, const void* gaddr) {
    asm volatile("cp.async.cg.shared.global [%0], [%1], 16;" :: "r"(saddr), "l"(gaddr));
}
#define CP_COMMIT() asm volatile("cp.async.commit_group;" ::: "memory")

__device__ __forceinline__ void ldsm_x4(uint32_t* r, uint32_t a) {
    asm volatile("ldmatrix.sync.aligned.m8n8.x4.shared.b16 {%0,%1,%2,%3}, [%4];"
                 : "=r"(r[0]), "=r"(r[1]), "=r"(r[2]), "=r"(r[3]) : "r"(a));
}
__device__ __forceinline__ void mma16816(float* d, const uint32_t* a, uint32_t b0, uint32_t b1) {
    asm volatile(
        "mma.sync.aligned.m16n8k16.row.col.f32.bf16.bf16.f32 "
        "{%0,%1,%2,%3}, {%4,%5,%6,%7}, {%8,%9}, {%0,%1,%2,%3};"
        : "+f"(d[0]), "+f"(d[1]), "+f"(d[2]), "+f"(d[3])
        : "r"(a[0]), "r"(a[1]), "r"(a[2]), "r"(a[3]), "r"(b0), "r"(b1));
}

// ============================ P1: reset + blockmax + W split ============================
__global__ void __launch_bounds__(256) k_prep1(const float* __restrict__ freq,
                                               const float* __restrict__ w) {
    int tid = threadIdx.x, bid = blockIdx.x;
    int gid = bid * 256 + tid;                   // 131072 threads

    if (gid < WID) g_cnt[gid] = 0;

    // W hi/lo split: 2 elems per thread
    {
        float2 wv = *(const float2*)(w + (size_t)gid * 2);
        __nv_bfloat16 h0 = __float2bfloat16(wv.x);
        __nv_bfloat16 h1 = __float2bfloat16(wv.y);
        __nv_bfloat162 hp(h0, h1);
        *(uint32_t*)&g_whi[(size_t)gid * 2] = *(uint32_t*)&hp;
        __nv_bfloat162 lp(__float2bfloat16(wv.x - __bfloat162float(h0)),
                          __float2bfloat16(wv.y - __bfloat162float(h1)));
        *(uint32_t*)&g_wlo[(size_t)gid * 2] = *(uint32_t*)&lp;
    }

    // block max of |freq|*scale: 4 elems per thread
    float4 f = *(const float4*)(freq + (size_t)gid * 4);
    float m = fmaxf(fmaxf(fabsf(f.x), fabsf(f.y)), fmaxf(fabsf(f.z), fabsf(f.w)))
              * SPECTRAL_SCALE;
    #pragma unroll
    for (int o = 16; o; o >>= 1) m = fmaxf(m, __shfl_xor_sync(0xffffffffu, m, o));
    __shared__ float s[8];
    int lane = tid & 31, wd = tid >> 5;
    if (lane == 0) s[wd] = m;
    __syncthreads();
    if (tid == 0) {
        float bm = s[0];
        #pragma unroll
        for (int i = 1; i < 8; ++i) bm = fmaxf(bm, s[i]);
        g_blockmax[bid] = bm;
    }
}

// ============================ P2: threshold -> compact lists ============================
__global__ void __launch_bounds__(256) k_thr(const float* __restrict__ freq,
                                             const float* __restrict__ alpha,
                                             const float* __restrict__ gate) {
    // reduce the 512 block maxes
    __shared__ float s[8];
    int tid = threadIdx.x;
    float m = fmaxf(g_blockmax[tid], g_blockmax[tid + 256]);
    #pragma unroll
    for (int o = 16; o; o >>= 1) m = fmaxf(m, __shfl_xor_sync(0xffffffffu, m, o));
    int lane = tid & 31, wd = tid >> 5;
    if (lane == 0) s[wd] = m;
    __syncthreads();
    float denom = s[0];
    #pragma unroll
    for (int i = 1; i < 8; ++i) denom = fmaxf(denom, s[i]);

    int base = (blockIdx.x * 256 + tid) * 4;
    float4 fv = *(const float4*)(freq + base);
    float4 av = *(const float4*)(alpha + base);
    float4 gv = *(const float4*)(gate + base);
    const float* fp = &fv.x;
    const float* ap = &av.x;
    const float* gp = &gv.x;
    #pragma unroll
    for (int u = 0; u < 4; ++u) {
        int i = base + u;
        float f = fp[u] * SPECTRAL_SCALE;
        float win;
        if (denom < 1e-8f) win = 1.f;
        else { float r = f / denom; win = expf(-ES_BETA * r * r); }
        float raw = ap[u] * gp[u];
        float mag = fabsf(raw) - TAU;
        if (mag > 0.f) {
            float t = copysignf(mag, raw) * win;
            if (t != 0.f) {
                int wdx = i & (WID - 1);
                int pos = atomicAdd(&g_cnt[wdx], 1);
                g_fnz[wdx * FTOT + pos] = f;
                g_tnz[wdx * FTOT + pos] = t;
            }
        }
    }
}

// ============================ P3: LayerNorm + spectral (warp per row) ============================
__global__ void __launch_bounds__(256) k_lnspec(const float* __restrict__ x,
                                                const float* __restrict__ gamma,
                                                const float* __restrict__ beta) {
    int lane = threadIdx.x & 31;
    int row = blockIdx.x * 8 + (threadIdx.x >> 5);
    const float4* xr = (const float4*)(x + (size_t)row * WID);
    float4 v[4];
    float s = 0.f, q = 0.f;
    #pragma unroll
    for (int i = 0; i < 4; ++i) {
        v[i] = xr[lane + 32 * i];
        s += v[i].x + v[i].y + v[i].z + v[i].w;
        q += v[i].x * v[i].x + v[i].y * v[i].y + v[i].z * v[i].z + v[i].w * v[i].w;
    }
    #pragma unroll
    for (int o = 16; o; o >>= 1) {
        s += __shfl_xor_sync(0xffffffffu, s, o);
        q += __shfl_xor_sync(0xffffffffu, q, o);
    }
    float mu = s * (1.f / WID);
    float inv = rsqrtf(q * (1.f / WID) - mu * mu + LN_EPS);

    float xn[16];
    #pragma unroll
    for (int i = 0; i < 4; ++i) {
        int cb = (lane + 32 * i) * 4;
        float4 g = ((const float4*)gamma)[lane + 32 * i];
        float4 b = ((const float4*)beta)[lane + 32 * i];
        float o0 = (v[i].x - mu) * inv * g.x + b.x;
        float o1 = (v[i].y - mu) * inv * g.y + b.y;
        float o2 = (v[i].z - mu) * inv * g.z + b.z;
        float o3 = (v[i].w - mu) * inv * g.w + b.w;
        xn[i * 4 + 0] = o0; xn[i * 4 + 1] = o1; xn[i * 4 + 2] = o2; xn[i * 4 + 3] = o3;
        __nv_bfloat16 h0 = __float2bfloat16(o0), h1 = __float2bfloat16(o1);
        __nv_bfloat16 h2 = __float2bfloat16(o2), h3 = __float2bfloat16(o3);
        __nv_bfloat162 hp0(h0, h1), hp1(h2, h3);
        *(uint2*)&g_ahi[(size_t)row * WID + cb] =
            make_uint2(*(uint32_t*)&hp0, *(uint32_t*)&hp1);
        __nv_bfloat162 lp0(__float2bfloat16(o0 - __bfloat162float(h0)),
                           __float2bfloat16(o1 - __bfloat162float(h1)));
        __nv_bfloat162 lp1(__float2bfloat16(o2 - __bfloat162float(h2)),
                           __float2bfloat16(o3 - __bfloat162float(h3)));
        *(uint2*)&g_alo[(size_t)row * WID + cb] =
            make_uint2(*(uint32_t*)&lp0, *(uint32_t*)&lp1);
    }

    // spectral: each lane owns 16 width positions (MMA inputs use full fp32 xn)
    float sv[16];
    float qq = 0.f;
    #pragma unroll
    for (int i = 0; i < 4; ++i) {
        #pragma unroll
        for (int u = 0; u < 4; ++u) {
            int wdx = (lane + 32 * i) * 4 + u;
            int cnt = g_cnt[wdx];
            const float* fp = g_fnz + wdx * FTOT;
            const float* tp = g_tnz + wdx * FTOT;
            float acc = 0.f;
            float xv = xn[i * 4 + u];
            for (int j = 0; j < cnt; ++j)
                acc += __sinf(xv * fp[j]) * tp[j];
            sv[i * 4 + u] = acc;
            qq += acc * acc;
        }
    }
    #pragma unroll
    for (int o = 16; o; o >>= 1) qq += __shfl_xor_sync(0xffffffffu, qq, o);
    float rinv = RHO * rsqrtf(qq * (1.f / WID) + EPS_RMS);
    #pragma unroll
    for (int i = 0; i < 4; ++i) {
        int cb = (lane + 32 * i) * 4;
        float4 o;
        o.x = sv[i * 4 + 0] * rinv; o.y = sv[i * 4 + 1] * rinv;
        o.z = sv[i * 4 + 2] * rinv; o.w = sv[i * 4 + 3] * rinv;
        *(float4*)(g_spec + (size_t)row * WID + cb) = o;
    }
}

// ============================ P4: HMMA GEMM (4 tiles/chunk, 3 passes) ============================
__global__ void __launch_bounds__(256, 1)
k_mma(const float* __restrict__ bias, float* __restrict__ out) {
    extern __shared__ char smem[];
    uint32_t sb = smem_u32(smem);
    int tid = threadIdx.x;
    int wid = tid >> 5, lane = tid & 31;
    int warp_m = wid & 1;        // 2 warps over M (64 rows each)
    int warp_n = wid >> 1;       // 4 warps over N (32 cols each)

    int bm = blockIdx.y * TM;
    int bn = blockIdx.x * TN;

    float acc[4][4][4];
    #pragma unroll
    for (int i = 0; i < 4; ++i)
        #pragma unroll
        for (int j = 0; j < 4; ++j)
            #pragma unroll
            for (int k = 0; k < 4; ++k) acc[i][j][k] = 0.f;

    auto load_iter = [&](int k0, int stg) {
        int kcol = k0 * KC;
        uint32_t base = sb + stg * STGB;
        #pragma unroll
        for (int it = 0; it < 4; ++it) {
            int idx = it * 256 + tid;     // 0..1023
            int row = idx >> 3;
            int c16 = idx & 7;
            uint32_t so = (uint32_t)(row * ROWB + c16 * 16);
            size_t ga = (size_t)(bm + row) * WID + kcol + c16 * 8;
            size_t gb = (size_t)(bn + row) * WID + kcol + c16 * 8;
            cp_async16(base + so,              g_ahi + ga);
            cp_async16(base + ATILEB + so,     g_alo + ga);
            cp_async16(base + 2 * ATILEB + so, g_whi + gb);
            cp_async16(base + 3 * ATILEB + so, g_wlo + gb);
        }
        CP_COMMIT();
    };

    load_iter(0, 0);

    for (int c = 0; c < NKCH; ++c) {
        if (c + 1 < NKCH) load_iter(c + 1, (c + 1) & 1);
        if (c + 1 < NKCH) asm volatile("cp.async.wait_group 1;" ::: "memory");
        else              asm volatile("cp.async.wait_group 0;" ::: "memory");
        __syncthreads();

        uint32_t base = sb + (c & 1) * STGB;
        #pragma unroll
        for (int ks = 0; ks < 4; ++ks) {
            uint32_t a_row_off =
                (uint32_t)((warp_m * 64 + (lane & 15)) * ROWB + (ks * 16 + (lane >> 4) * 8) * 2);
            uint32_t af_hi[4][4], af_lo[4][4];
            #pragma unroll
            for (int mt = 0; mt < 4; ++mt) {
                uint32_t addr = base + a_row_off + (uint32_t)(mt * 16 * ROWB);
                ldsm_x4(af_hi[mt], addr);
                ldsm_x4(af_lo[mt], addr + ATILEB);
            }
            uint32_t bf_hi[2][4], bf_lo[2][4];
            #pragma unroll
            for (int bt = 0; bt < 2; ++bt) {
                int nrow = warp_n * 32 + bt * 16 + (lane & 7) + ((lane >> 4) << 3);
                uint32_t addr = base + 2 * ATILEB
                    + (uint32_t)(nrow * ROWB + (ks * 16 + ((lane >> 3) & 1) * 8) * 2);
                ldsm_x4(bf_hi[bt], addr);
                ldsm_x4(bf_lo[bt], addr + ATILEB);
            }
            #pragma unroll
            for (int mt = 0; mt < 4; ++mt)
                #pragma unroll
                for (int nt = 0; nt < 4; ++nt) {
                    int bt = nt >> 1, bi = (nt & 1) * 2;
                    mma16816(acc[mt][nt], af_hi[mt], bf_hi[bt][bi], bf_hi[bt][bi + 1]);
                    mma16816(acc[mt][nt], af_hi[mt], bf_lo[bt][bi], bf_lo[bt][bi + 1]);
                    mma16816(acc[mt][nt], af_lo[mt], bf_hi[bt][bi], bf_hi[bt][bi + 1]);
                }
        }
        __syncthreads();
    }

    // ---- epilogue: bias + exact GELU + spectral add ----
    #pragma unroll
    for (int mt = 0; mt < 4; ++mt) {
        int r0 = bm + warp_m * 64 + mt * 16 + (lane >> 2);
        #pragma unroll
        for (int nt = 0; nt < 4; ++nt) {
            int c0 = bn + warp_n * 32 + nt * 8 + (lane & 3) * 2;
            float b0 = bias[c0], b1 = bias[c0 + 1];
            #pragma unroll
            for (int h = 0; h < 2; ++h) {
                int r = r0 + h * 8;
                float v0 = acc[mt][nt][h * 2 + 0] + b0;
                float v1 = acc[mt][nt][h * 2 + 1] + b1;
                float g0 = 0.5f * v0 * (1.f + erff(v0 * 0.70710678118654752f));
                float g1 = 0.5f * v1 * (1.f + erff(v1 * 0.70710678118654752f));
                float2 sp = *(const float2*)(g_spec + (size_t)r * WID + c0);
                float2 o = make_float2(g0 + sp.x, g1 + sp.y);
                *(float2*)(out + (size_t)r * WID + c0) = o;
            }
        }
    }
}

// ============================ launch ============================
extern "C" void kernel_launch(void* const* d_in, const int* in_sizes, int n_in,
                              void* d_out, int out_size) {
    const float* x     = (const float*)d_in[0];
    const float* freq  = (const float*)d_in[1];
    const float* alpha = (const float*)d_in[2];
    const float* gate  = (const float*)d_in[3];
    const float* ln_g  = (const float*)d_in[4];
    const float* ln_b  = (const float*)d_in[5];
    const float* w_loc = (const float*)d_in[6];
    const float* b_loc = (const float*)d_in[7];
    float* out = (float*)d_out;

    static bool attr_done = false;
    if (!attr_done) {
        cudaFuncSetAttribute(k_mma, cudaFuncAttributeMaxDynamicSharedMemorySize, SMEM_TOTAL);
        attr_done = true;
    }

    k_prep1<<<512, 256>>>(freq, w_loc);
    k_thr<<<512, 256>>>(freq, alpha, gate);
    k_lnspec<<<512, 256>>>(x, ln_g, ln_b);
    k_mma<<<dim3(WID / TN, NTOK / TM), 256, SMEM_TOTAL>>>(b_loc, out);
}

// round 9
// speedup vs baseline: 2.2624x; 1.0585x over previous
#include <cuda_runtime.h>
#include <cuda_bf16.h>
#include <cstdint>
#include <math.h>

#define NTOK 4096
#define WID  512
#define FTOT 1024
#define SPECTRAL_SCALE 0.8f
#define ES_BETA 6.0f
#define TAU 0.001f
#define RHO 0.25f
#define LN_EPS 1e-5f
#define EPS_RMS 1e-8f

// ----- GEMM tiling -----
#define TM 128
#define TN 64
#define KC 64             // bf16 K elems per outer chunk
#define NKCH 8            // 512 / 64
#define ROWB 144          // padded row bytes: 72 bf16 (conflict-free ldmatrix)
#define ATB (128 * ROWB)            // A tile bytes (128 rows) = 18432
#define WTB (64 * ROWB)             // W tile bytes (64 rows)  = 9216
#define OFF_AHI 0
#define OFF_ALO ATB
#define OFF_WHI (2 * ATB)
#define OFF_WLO (2 * ATB + WTB)
#define STGB (2 * ATB + 2 * WTB)    // 55296
#define SMEM_TOTAL (2 * STGB)       // 110592 (double buffer) -> 2 CTAs/SM

// Scratch (no cudaMalloc allowed)
__device__ __nv_bfloat16 g_ahi[NTOK * WID];
__device__ __nv_bfloat16 g_alo[NTOK * WID];
__device__ __nv_bfloat16 g_whi[WID * WID];
__device__ __nv_bfloat16 g_wlo[WID * WID];
__device__ float g_spec[NTOK * WID];
__device__ float g_fnz[WID * FTOT];
__device__ float g_tnz[WID * FTOT];
__device__ int   g_cnt[WID];
__device__ float g_blockmax[512];

// ============================ PTX helpers ============================
__device__ __forceinline__ uint32_t smem_u32(const void* p) {
    uint32_t a;
    asm("{ .reg .u64 t; cvta.to.shared.u64 t, %1; cvt.u32.u64 %0, t; }" : "=r"(a) : "l"(p));
    return a;
}
__device__ __forceinline__ void cp_async16(uint32_t saddr, const void* gaddr) {
    asm volatile("cp.async.cg.shared.global [%0], [%1], 16;" :: "r"(saddr), "l"(gaddr));
}
#define CP_COMMIT() asm volatile("cp.async.commit_group;" ::: "memory")

__device__ __forceinline__ void ldsm_x4(uint32_t* r, uint32_t a) {
    asm volatile("ldmatrix.sync.aligned.m8n8.x4.shared.b16 {%0,%1,%2,%3}, [%4];"
                 : "=r"(r[0]), "=r"(r[1]), "=r"(r[2]), "=r"(r[3]) : "r"(a));
}
__device__ __forceinline__ void mma16816(float* d, const uint32_t* a, uint32_t b0, uint32_t b1) {
    asm volatile(
        "mma.sync.aligned.m16n8k16.row.col.f32.bf16.bf16.f32 "
        "{%0,%1,%2,%3}, {%4,%5,%6,%7}, {%8,%9}, {%0,%1,%2,%3};"
        : "+f"(d[0]), "+f"(d[1]), "+f"(d[2]), "+f"(d[3])
        : "r"(a[0]), "r"(a[1]), "r"(a[2]), "r"(a[3]), "r"(b0), "r"(b1));
}

// ============================ P1: reset + blockmax + W split ============================
__global__ void __launch_bounds__(256) k_prep1(const float* __restrict__ freq,
                                               const float* __restrict__ w) {
    int tid = threadIdx.x, bid = blockIdx.x;
    int gid = bid * 256 + tid;                   // 131072 threads

    if (gid < WID) g_cnt[gid] = 0;

    {
        float2 wv = *(const float2*)(w + (size_t)gid * 2);
        __nv_bfloat16 h0 = __float2bfloat16(wv.x);
        __nv_bfloat16 h1 = __float2bfloat16(wv.y);
        __nv_bfloat162 hp(h0, h1);
        *(uint32_t*)&g_whi[(size_t)gid * 2] = *(uint32_t*)&hp;
        __nv_bfloat162 lp(__float2bfloat16(wv.x - __bfloat162float(h0)),
                          __float2bfloat16(wv.y - __bfloat162float(h1)));
        *(uint32_t*)&g_wlo[(size_t)gid * 2] = *(uint32_t*)&lp;
    }

    float4 f = *(const float4*)(freq + (size_t)gid * 4);
    float m = fmaxf(fmaxf(fabsf(f.x), fabsf(f.y)), fmaxf(fabsf(f.z), fabsf(f.w)))
              * SPECTRAL_SCALE;
    #pragma unroll
    for (int o = 16; o; o >>= 1) m = fmaxf(m, __shfl_xor_sync(0xffffffffu, m, o));
    __shared__ float s[8];
    int lane = tid & 31, wd = tid >> 5;
    if (lane == 0) s[wd] = m;
    __syncthreads();
    if (tid == 0) {
        float bm = s[0];
        #pragma unroll
        for (int i = 1; i < 8; ++i) bm = fmaxf(bm, s[i]);
        g_blockmax[bid] = bm;
    }
}

// ============================ P2: threshold -> compact lists ============================
__global__ void __launch_bounds__(256) k_thr(const float* __restrict__ freq,
                                             const float* __restrict__ alpha,
                                             const float* __restrict__ gate) {
    __shared__ float s[8];
    int tid = threadIdx.x;
    float m = fmaxf(g_blockmax[tid], g_blockmax[tid + 256]);
    #pragma unroll
    for (int o = 16; o; o >>= 1) m = fmaxf(m, __shfl_xor_sync(0xffffffffu, m, o));
    int lane = tid & 31, wd = tid >> 5;
    if (lane == 0) s[wd] = m;
    __syncthreads();
    float denom = s[0];
    #pragma unroll
    for (int i = 1; i < 8; ++i) denom = fmaxf(denom, s[i]);

    int base = (blockIdx.x * 256 + tid) * 4;
    float4 fv = *(const float4*)(freq + base);
    float4 av = *(const float4*)(alpha + base);
    float4 gv = *(const float4*)(gate + base);
    const float* fp = &fv.x;
    const float* ap = &av.x;
    const float* gp = &gv.x;
    #pragma unroll
    for (int u = 0; u < 4; ++u) {
        int i = base + u;
        float f = fp[u] * SPECTRAL_SCALE;
        float win;
        if (denom < 1e-8f) win = 1.f;
        else { float r = f / denom; win = expf(-ES_BETA * r * r); }
        float raw = ap[u] * gp[u];
        float mag = fabsf(raw) - TAU;
        if (mag > 0.f) {
            float t = copysignf(mag, raw) * win;
            if (t != 0.f) {
                int wdx = i & (WID - 1);
                int pos = atomicAdd(&g_cnt[wdx], 1);
                g_fnz[wdx * FTOT + pos] = f;
                g_tnz[wdx * FTOT + pos] = t;
            }
        }
    }
}

// ============================ P3: LayerNorm + spectral (warp per row) ============================
__global__ void __launch_bounds__(256) k_lnspec(const float* __restrict__ x,
                                                const float* __restrict__ gamma,
                                                const float* __restrict__ beta) {
    int lane = threadIdx.x & 31;
    int row = blockIdx.x * 8 + (threadIdx.x >> 5);
    const float4* xr = (const float4*)(x + (size_t)row * WID);
    float4 v[4];
    float s = 0.f, q = 0.f;
    #pragma unroll
    for (int i = 0; i < 4; ++i) {
        v[i] = xr[lane + 32 * i];
        s += v[i].x + v[i].y + v[i].z + v[i].w;
        q += v[i].x * v[i].x + v[i].y * v[i].y + v[i].z * v[i].z + v[i].w * v[i].w;
    }
    #pragma unroll
    for (int o = 16; o; o >>= 1) {
        s += __shfl_xor_sync(0xffffffffu, s, o);
        q += __shfl_xor_sync(0xffffffffu, q, o);
    }
    float mu = s * (1.f / WID);
    float inv = rsqrtf(q * (1.f / WID) - mu * mu + LN_EPS);

    float xn[16];
    #pragma unroll
    for (int i = 0; i < 4; ++i) {
        int cb = (lane + 32 * i) * 4;
        float4 g = ((const float4*)gamma)[lane + 32 * i];
        float4 b = ((const float4*)beta)[lane + 32 * i];
        float o0 = (v[i].x - mu) * inv * g.x + b.x;
        float o1 = (v[i].y - mu) * inv * g.y + b.y;
        float o2 = (v[i].z - mu) * inv * g.z + b.z;
        float o3 = (v[i].w - mu) * inv * g.w + b.w;
        xn[i * 4 + 0] = o0; xn[i * 4 + 1] = o1; xn[i * 4 + 2] = o2; xn[i * 4 + 3] = o3;
        __nv_bfloat16 h0 = __float2bfloat16(o0), h1 = __float2bfloat16(o1);
        __nv_bfloat16 h2 = __float2bfloat16(o2), h3 = __float2bfloat16(o3);
        __nv_bfloat162 hp0(h0, h1), hp1(h2, h3);
        *(uint2*)&g_ahi[(size_t)row * WID + cb] =
            make_uint2(*(uint32_t*)&hp0, *(uint32_t*)&hp1);
        __nv_bfloat162 lp0(__float2bfloat16(o0 - __bfloat162float(h0)),
                           __float2bfloat16(o1 - __bfloat162float(h1)));
        __nv_bfloat162 lp1(__float2bfloat16(o2 - __bfloat162float(h2)),
                           __float2bfloat16(o3 - __bfloat162float(h3)));
        *(uint2*)&g_alo[(size_t)row * WID + cb] =
            make_uint2(*(uint32_t*)&lp0, *(uint32_t*)&lp1);
    }

    float sv[16];
    float qq = 0.f;
    #pragma unroll
    for (int i = 0; i < 4; ++i) {
        #pragma unroll
        for (int u = 0; u < 4; ++u) {
            int wdx = (lane + 32 * i) * 4 + u;
            int cnt = g_cnt[wdx];
            const float* fp = g_fnz + wdx * FTOT;
            const float* tp = g_tnz + wdx * FTOT;
            float acc = 0.f;
            float xv = xn[i * 4 + u];
            for (int j = 0; j < cnt; ++j)
                acc += __sinf(xv * fp[j]) * tp[j];
            sv[i * 4 + u] = acc;
            qq += acc * acc;
        }
    }
    #pragma unroll
    for (int o = 16; o; o >>= 1) qq += __shfl_xor_sync(0xffffffffu, qq, o);
    float rinv = RHO * rsqrtf(qq * (1.f / WID) + EPS_RMS);
    #pragma unroll
    for (int i = 0; i < 4; ++i) {
        int cb = (lane + 32 * i) * 4;
        float4 o;
        o.x = sv[i * 4 + 0] * rinv; o.y = sv[i * 4 + 1] * rinv;
        o.z = sv[i * 4 + 2] * rinv; o.w = sv[i * 4 + 3] * rinv;
        *(float4*)(g_spec + (size_t)row * WID + cb) = o;
    }
}

// ============================ P4: HMMA GEMM (128x64 tiles, 2 CTAs/SM) ============================
__global__ void __launch_bounds__(256, 2)
k_mma(const float* __restrict__ bias, float* __restrict__ out) {
    extern __shared__ char smem[];
    uint32_t sb = smem_u32(smem);
    int tid = threadIdx.x;
    int wid = tid >> 5, lane = tid & 31;
    int warp_m = wid & 3;        // 4 warps over M (32 rows each)
    int warp_n = wid >> 2;       // 2 warps over N (32 cols each)

    int bm = blockIdx.y * TM;
    int bn = blockIdx.x * TN;

    float acc[2][4][4];
    #pragma unroll
    for (int i = 0; i < 2; ++i)
        #pragma unroll
        for (int j = 0; j < 4; ++j)
            #pragma unroll
            for (int k = 0; k < 4; ++k) acc[i][j][k] = 0.f;

    auto load_iter = [&](int k0, int stg) {
        int kcol = k0 * KC;
        uint32_t base = sb + stg * STGB;
        // A tiles: 128 rows x 8 sixteen-byte cols = 1024 slots, 4 per thread
        #pragma unroll
        for (int it = 0; it < 4; ++it) {
            int idx = it * 256 + tid;
            int row = idx >> 3;
            int c16 = idx & 7;
            uint32_t so = (uint32_t)(row * ROWB + c16 * 16);
            size_t ga = (size_t)(bm + row) * WID + kcol + c16 * 8;
            cp_async16(base + OFF_AHI + so, g_ahi + ga);
            cp_async16(base + OFF_ALO + so, g_alo + ga);
        }
        // W tiles: 64 rows x 8 = 512 slots, 2 per thread
        #pragma unroll
        for (int it = 0; it < 2; ++it) {
            int idx = it * 256 + tid;
            int row = idx >> 3;
            int c16 = idx & 7;
            uint32_t so = (uint32_t)(row * ROWB + c16 * 16);
            size_t gb = (size_t)(bn + row) * WID + kcol + c16 * 8;
            cp_async16(base + OFF_WHI + so, g_whi + gb);
            cp_async16(base + OFF_WLO + so, g_wlo + gb);
        }
        CP_COMMIT();
    };

    load_iter(0, 0);

    for (int c = 0; c < NKCH; ++c) {
        if (c + 1 < NKCH) load_iter(c + 1, (c + 1) & 1);
        if (c + 1 < NKCH) asm volatile("cp.async.wait_group 1;" ::: "memory");
        else              asm volatile("cp.async.wait_group 0;" ::: "memory");
        __syncthreads();

        uint32_t base = sb + (c & 1) * STGB;
        #pragma unroll
        for (int ks = 0; ks < 4; ++ks) {
            uint32_t a_row_off =
                (uint32_t)((warp_m * 32 + (lane & 15)) * ROWB + (ks * 16 + (lane >> 4) * 8) * 2);
            uint32_t af_hi[2][4], af_lo[2][4];
            #pragma unroll
            for (int mt = 0; mt < 2; ++mt) {
                uint32_t addr = base + a_row_off + (uint32_t)(mt * 16 * ROWB);
                ldsm_x4(af_hi[mt], addr + OFF_AHI);
                ldsm_x4(af_lo[mt], addr + OFF_ALO);
            }
            uint32_t bf_hi[2][4], bf_lo[2][4];
            #pragma unroll
            for (int bt = 0; bt < 2; ++bt) {
                int nrow = warp_n * 32 + bt * 16 + (lane & 7) + ((lane >> 4) << 3);
                uint32_t addr = base
                    + (uint32_t)(nrow * ROWB + (ks * 16 + ((lane >> 3) & 1) * 8) * 2);
                ldsm_x4(bf_hi[bt], addr + OFF_WHI);
                ldsm_x4(bf_lo[bt], addr + OFF_WLO);
            }
            #pragma unroll
            for (int mt = 0; mt < 2; ++mt)
                #pragma unroll
                for (int nt = 0; nt < 4; ++nt) {
                    int bt = nt >> 1, bi = (nt & 1) * 2;
                    mma16816(acc[mt][nt], af_hi[mt], bf_hi[bt][bi], bf_hi[bt][bi + 1]);
                    mma16816(acc[mt][nt], af_hi[mt], bf_lo[bt][bi], bf_lo[bt][bi + 1]);
                    mma16816(acc[mt][nt], af_lo[mt], bf_hi[bt][bi], bf_hi[bt][bi + 1]);
                }
        }
        __syncthreads();
    }

    // ---- epilogue: bias + exact GELU + spectral add ----
    #pragma unroll
    for (int mt = 0; mt < 2; ++mt) {
        int r0 = bm + warp_m * 32 + mt * 16 + (lane >> 2);
        #pragma unroll
        for (int nt = 0; nt < 4; ++nt) {
            int c0 = bn + warp_n * 32 + nt * 8 + (lane & 3) * 2;
            float b0 = bias[c0], b1 = bias[c0 + 1];
            #pragma unroll
            for (int h = 0; h < 2; ++h) {
                int r = r0 + h * 8;
                float v0 = acc[mt][nt][h * 2 + 0] + b0;
                float v1 = acc[mt][nt][h * 2 + 1] + b1;
                float g0 = 0.5f * v0 * (1.f + erff(v0 * 0.70710678118654752f));
                float g1 = 0.5f * v1 * (1.f + erff(v1 * 0.70710678118654752f));
                float2 sp = *(const float2*)(g_spec + (size_t)r * WID + c0);
                float2 o = make_float2(g0 + sp.x, g1 + sp.y);
                *(float2*)(out + (size_t)r * WID + c0) = o;
            }
        }
    }
}

// ============================ launch ============================
extern "C" void kernel_launch(void* const* d_in, const int* in_sizes, int n_in,
                              void* d_out, int out_size) {
    const float* x     = (const float*)d_in[0];
    const float* freq  = (const float*)d_in[1];
    const float* alpha = (const float*)d_in[2];
    const float* gate  = (const float*)d_in[3];
    const float* ln_g  = (const float*)d_in[4];
    const float* ln_b  = (const float*)d_in[5];
    const float* w_loc = (const float*)d_in[6];
    const float* b_loc = (const float*)d_in[7];
    float* out = (float*)d_out;

    static bool attr_done = false;
    if (!attr_done) {
        cudaFuncSetAttribute(k_mma, cudaFuncAttributeMaxDynamicSharedMemorySize, SMEM_TOTAL);
        attr_done = true;
    }

    k_prep1<<<512, 256>>>(freq, w_loc);
    k_thr<<<512, 256>>>(freq, alpha, gate);
    k_lnspec<<<512, 256>>>(x, ln_g, ln_b);
    k_mma<<<dim3(WID / TN, NTOK / TM), 256, SMEM_TOTAL>>>(b_loc, out);
}

// round 10
// speedup vs baseline: 2.6805x; 1.1848x over previous
#include <cuda_runtime.h>
#include <cuda_fp16.h>
#include <cstdint>
#include <math.h>

#define NTOK 4096
#define WID  512
#define FTOT 1024
#define SPECTRAL_SCALE 0.8f
#define ES_BETA 6.0f
#define TAU 0.001f
#define RHO 0.25f
#define LN_EPS 1e-5f
#define EPS_RMS 1e-8f

// ----- GEMM tiling -----
#define TM 128
#define TN 64
#define KC 64             // fp16 K elems per outer chunk
#define NKCH 8            // 512 / 64
#define ROWB 144          // padded row bytes: 72 halves (conflict-free ldmatrix)
#define ATB (128 * ROWB)            // A tile bytes = 18432
#define WTB (64 * ROWB)             // W tile bytes = 9216
#define OFF_A  0
#define OFF_WH ATB
#define OFF_WL (ATB + WTB)
#define STGB (ATB + 2 * WTB)        // 36864
#define SMEM_TOTAL (2 * STGB)       // 73728 (double buffer) -> 2 CTAs/SM

// Scratch (no cudaMalloc allowed)
__device__ __half g_ah[NTOK * WID];
__device__ __half g_whi[WID * WID];
__device__ __half g_wlo[WID * WID];
__device__ float g_spec[NTOK * WID];
__device__ float g_fnz[WID * FTOT];
__device__ float g_tnz[WID * FTOT];
__device__ int   g_cnt[WID];
__device__ float g_blockmax[512];

// ============================ PTX helpers ============================
__device__ __forceinline__ uint32_t smem_u32(const void* p) {
    uint32_t a;
    asm("{ .reg .u64 t; cvta.to.shared.u64 t, %1; cvt.u32.u64 %0, t; }" : "=r"(a) : "l"(p));
    return a;
}
__device__ __forceinline__ void cp_async16(uint32_t saddr, const void* gaddr) {
    asm volatile("cp.async.cg.shared.global [%0], [%1], 16;" :: "r"(saddr), "l"(gaddr));
}
#define CP_COMMIT() asm volatile("cp.async.commit_group;" ::: "memory")

__device__ __forceinline__ void ldsm_x4(uint32_t* r, uint32_t a) {
    asm volatile("ldmatrix.sync.aligned.m8n8.x4.shared.b16 {%0,%1,%2,%3}, [%4];"
                 : "=r"(r[0]), "=r"(r[1]), "=r"(r[2]), "=r"(r[3]) : "r"(a));
}
__device__ __forceinline__ void mma16816(float* d, const uint32_t* a, uint32_t b0, uint32_t b1) {
    asm volatile(
        "mma.sync.aligned.m16n8k16.row.col.f32.f16.f16.f32 "
        "{%0,%1,%2,%3}, {%4,%5,%6,%7}, {%8,%9}, {%0,%1,%2,%3};"
        : "+f"(d[0]), "+f"(d[1]), "+f"(d[2]), "+f"(d[3])
        : "r"(a[0]), "r"(a[1]), "r"(a[2]), "r"(a[3]), "r"(b0), "r"(b1));
}

// ============================ P1: reset + blockmax + W split ============================
__global__ void __launch_bounds__(256) k_prep1(const float* __restrict__ freq,
                                               const float* __restrict__ w) {
    int tid = threadIdx.x, bid = blockIdx.x;
    int gid = bid * 256 + tid;                   // 131072 threads

    if (gid < WID) g_cnt[gid] = 0;

    {
        float2 wv = *(const float2*)(w + (size_t)gid * 2);
        __half h0 = __float2half(wv.x);
        __half h1 = __float2half(wv.y);
        __half2 hp = __halves2half2(h0, h1);
        *(uint32_t*)&g_whi[(size_t)gid * 2] = *(uint32_t*)&hp;
        __half2 lp = __halves2half2(__float2half(wv.x - __half2float(h0)),
                                    __float2half(wv.y - __half2float(h1)));
        *(uint32_t*)&g_wlo[(size_t)gid * 2] = *(uint32_t*)&lp;
    }

    float4 f = *(const float4*)(freq + (size_t)gid * 4);
    float m = fmaxf(fmaxf(fabsf(f.x), fabsf(f.y)), fmaxf(fabsf(f.z), fabsf(f.w)))
              * SPECTRAL_SCALE;
    #pragma unroll
    for (int o = 16; o; o >>= 1) m = fmaxf(m, __shfl_xor_sync(0xffffffffu, m, o));
    __shared__ float s[8];
    int lane = tid & 31, wd = tid >> 5;
    if (lane == 0) s[wd] = m;
    __syncthreads();
    if (tid == 0) {
        float bm = s[0];
        #pragma unroll
        for (int i = 1; i < 8; ++i) bm = fmaxf(bm, s[i]);
        g_blockmax[bid] = bm;
    }
}

// ============================ P2: threshold -> compact lists ============================
__global__ void __launch_bounds__(256) k_thr(const float* __restrict__ freq,
                                             const float* __restrict__ alpha,
                                             const float* __restrict__ gate) {
    __shared__ float s[8];
    int tid = threadIdx.x;
    float m = fmaxf(g_blockmax[tid], g_blockmax[tid + 256]);
    #pragma unroll
    for (int o = 16; o; o >>= 1) m = fmaxf(m, __shfl_xor_sync(0xffffffffu, m, o));
    int lane = tid & 31, wd = tid >> 5;
    if (lane == 0) s[wd] = m;
    __syncthreads();
    float denom = s[0];
    #pragma unroll
    for (int i = 1; i < 8; ++i) denom = fmaxf(denom, s[i]);

    int base = (blockIdx.x * 256 + tid) * 4;
    float4 fv = *(const float4*)(freq + base);
    float4 av = *(const float4*)(alpha + base);
    float4 gv = *(const float4*)(gate + base);
    const float* fp = &fv.x;
    const float* ap = &av.x;
    const float* gp = &gv.x;
    #pragma unroll
    for (int u = 0; u < 4; ++u) {
        int i = base + u;
        float f = fp[u] * SPECTRAL_SCALE;
        float win;
        if (denom < 1e-8f) win = 1.f;
        else { float r = f / denom; win = expf(-ES_BETA * r * r); }
        float raw = ap[u] * gp[u];
        float mag = fabsf(raw) - TAU;
        if (mag > 0.f) {
            float t = copysignf(mag, raw) * win;
            if (t != 0.f) {
                int wdx = i & (WID - 1);
                int pos = atomicAdd(&g_cnt[wdx], 1);
                g_fnz[wdx * FTOT + pos] = f;
                g_tnz[wdx * FTOT + pos] = t;
            }
        }
    }
}

// ============================ P3: LayerNorm + spectral (warp per row) ============================
__global__ void __launch_bounds__(256) k_lnspec(const float* __restrict__ x,
                                                const float* __restrict__ gamma,
                                                const float* __restrict__ beta) {
    int lane = threadIdx.x & 31;
    int row = blockIdx.x * 8 + (threadIdx.x >> 5);
    const float4* xr = (const float4*)(x + (size_t)row * WID);
    float4 v[4];
    float s = 0.f, q = 0.f;
    #pragma unroll
    for (int i = 0; i < 4; ++i) {
        v[i] = xr[lane + 32 * i];
        s += v[i].x + v[i].y + v[i].z + v[i].w;
        q += v[i].x * v[i].x + v[i].y * v[i].y + v[i].z * v[i].z + v[i].w * v[i].w;
    }
    #pragma unroll
    for (int o = 16; o; o >>= 1) {
        s += __shfl_xor_sync(0xffffffffu, s, o);
        q += __shfl_xor_sync(0xffffffffu, q, o);
    }
    float mu = s * (1.f / WID);
    float inv = rsqrtf(q * (1.f / WID) - mu * mu + LN_EPS);

    float xn[16];
    #pragma unroll
    for (int i = 0; i < 4; ++i) {
        int cb = (lane + 32 * i) * 4;
        float4 g = ((const float4*)gamma)[lane + 32 * i];
        float4 b = ((const float4*)beta)[lane + 32 * i];
        float o0 = (v[i].x - mu) * inv * g.x + b.x;
        float o1 = (v[i].y - mu) * inv * g.y + b.y;
        float o2 = (v[i].z - mu) * inv * g.z + b.z;
        float o3 = (v[i].w - mu) * inv * g.w + b.w;
        xn[i * 4 + 0] = o0; xn[i * 4 + 1] = o1; xn[i * 4 + 2] = o2; xn[i * 4 + 3] = o3;
        __half2 hp0 = __halves2half2(__float2half(o0), __float2half(o1));
        __half2 hp1 = __halves2half2(__float2half(o2), __float2half(o3));
        *(uint2*)&g_ah[(size_t)row * WID + cb] =
            make_uint2(*(uint32_t*)&hp0, *(uint32_t*)&hp1);
    }

    float sv[16];
    float qq = 0.f;
    #pragma unroll
    for (int i = 0; i < 4; ++i) {
        #pragma unroll
        for (int u = 0; u < 4; ++u) {
            int wdx = (lane + 32 * i) * 4 + u;
            int cnt = g_cnt[wdx];
            const float* fp = g_fnz + wdx * FTOT;
            const float* tp = g_tnz + wdx * FTOT;
            float acc = 0.f;
            float xv = xn[i * 4 + u];
            for (int j = 0; j < cnt; ++j)
                acc += __sinf(xv * fp[j]) * tp[j];
            sv[i * 4 + u] = acc;
            qq += acc * acc;
        }
    }
    #pragma unroll
    for (int o = 16; o; o >>= 1) qq += __shfl_xor_sync(0xffffffffu, qq, o);
    float rinv = RHO * rsqrtf(qq * (1.f / WID) + EPS_RMS);
    #pragma unroll
    for (int i = 0; i < 4; ++i) {
        int cb = (lane + 32 * i) * 4;
        float4 o;
        o.x = sv[i * 4 + 0] * rinv; o.y = sv[i * 4 + 1] * rinv;
        o.z = sv[i * 4 + 2] * rinv; o.w = sv[i * 4 + 3] * rinv;
        *(float4*)(g_spec + (size_t)row * WID + cb) = o;
    }
}

// ============================ P4: HMMA GEMM (fp16 2-pass, 128x64, 2 CTAs/SM) ============================
__global__ void __launch_bounds__(256, 2)
k_mma(const float* __restrict__ bias, float* __restrict__ out) {
    extern __shared__ char smem[];
    uint32_t sb = smem_u32(smem);
    int tid = threadIdx.x;
    int wid = tid >> 5, lane = tid & 31;
    int warp_m = wid & 3;        // 4 warps over M (32 rows each)
    int warp_n = wid >> 2;       // 2 warps over N (32 cols each)

    int bm = blockIdx.y * TM;
    int bn = blockIdx.x * TN;

    float acc[2][4][4];
    #pragma unroll
    for (int i = 0; i < 2; ++i)
        #pragma unroll
        for (int j = 0; j < 4; ++j)
            #pragma unroll
            for (int k = 0; k < 4; ++k) acc[i][j][k] = 0.f;

    auto load_iter = [&](int k0, int stg) {
        int kcol = k0 * KC;
        uint32_t base = sb + stg * STGB;
        // A tile: 128 rows x 8 sixteen-byte cols = 1024 slots, 4 per thread
        #pragma unroll
        for (int it = 0; it < 4; ++it) {
            int idx = it * 256 + tid;
            int row = idx >> 3;
            int c16 = idx & 7;
            uint32_t so = (uint32_t)(row * ROWB + c16 * 16);
            cp_async16(base + OFF_A + so, g_ah + (size_t)(bm + row) * WID + kcol + c16 * 8);
        }
        // W tiles: 64 rows x 8 = 512 slots, 2 per thread each
        #pragma unroll
        for (int it = 0; it < 2; ++it) {
            int idx = it * 256 + tid;
            int row = idx >> 3;
            int c16 = idx & 7;
            uint32_t so = (uint32_t)(row * ROWB + c16 * 16);
            size_t gb = (size_t)(bn + row) * WID + kcol + c16 * 8;
            cp_async16(base + OFF_WH + so, g_whi + gb);
            cp_async16(base + OFF_WL + so, g_wlo + gb);
        }
        CP_COMMIT();
    };

    load_iter(0, 0);

    for (int c = 0; c < NKCH; ++c) {
        if (c + 1 < NKCH) load_iter(c + 1, (c + 1) & 1);
        if (c + 1 < NKCH) asm volatile("cp.async.wait_group 1;" ::: "memory");
        else              asm volatile("cp.async.wait_group 0;" ::: "memory");
        __syncthreads();

        uint32_t base = sb + (c & 1) * STGB;
        #pragma unroll
        for (int ks = 0; ks < 4; ++ks) {
            uint32_t a_row_off =
                (uint32_t)((warp_m * 32 + (lane & 15)) * ROWB + (ks * 16 + (lane >> 4) * 8) * 2);
            uint32_t af[2][4];
            #pragma unroll
            for (int mt = 0; mt < 2; ++mt) {
                uint32_t addr = base + OFF_A + a_row_off + (uint32_t)(mt * 16 * ROWB);
                ldsm_x4(af[mt], addr);
            }
            uint32_t bf_hi[2][4], bf_lo[2][4];
            #pragma unroll
            for (int bt = 0; bt < 2; ++bt) {
                int nrow = warp_n * 32 + bt * 16 + (lane & 7) + ((lane >> 4) << 3);
                uint32_t addr = base
                    + (uint32_t)(nrow * ROWB + (ks * 16 + ((lane >> 3) & 1) * 8) * 2);
                ldsm_x4(bf_hi[bt], addr + OFF_WH);
                ldsm_x4(bf_lo[bt], addr + OFF_WL);
            }
            #pragma unroll
            for (int mt = 0; mt < 2; ++mt)
                #pragma unroll
                for (int nt = 0; nt < 4; ++nt) {
                    int bt = nt >> 1, bi = (nt & 1) * 2;
                    mma16816(acc[mt][nt], af[mt], bf_hi[bt][bi], bf_hi[bt][bi + 1]);
                    mma16816(acc[mt][nt], af[mt], bf_lo[bt][bi], bf_lo[bt][bi + 1]);
                }
        }
        __syncthreads();
    }

    // ---- epilogue: bias + exact GELU + spectral add ----
    #pragma unroll
    for (int mt = 0; mt < 2; ++mt) {
        int r0 = bm + warp_m * 32 + mt * 16 + (lane >> 2);
        #pragma unroll
        for (int nt = 0; nt < 4; ++nt) {
            int c0 = bn + warp_n * 32 + nt * 8 + (lane & 3) * 2;
            float b0 = bias[c0], b1 = bias[c0 + 1];
            #pragma unroll
            for (int h = 0; h < 2; ++h) {
                int r = r0 + h * 8;
                float v0 = acc[mt][nt][h * 2 + 0] + b0;
                float v1 = acc[mt][nt][h * 2 + 1] + b1;
                float g0 = 0.5f * v0 * (1.f + erff(v0 * 0.70710678118654752f));
                float g1 = 0.5f * v1 * (1.f + erff(v1 * 0.70710678118654752f));
                float2 sp = *(const float2*)(g_spec + (size_t)r * WID + c0);
                float2 o = make_float2(g0 + sp.x, g1 + sp.y);
                *(float2*)(out + (size_t)r * WID + c0) = o;
            }
        }
    }
}

// ============================ launch ============================
extern "C" void kernel_launch(void* const* d_in, const int* in_sizes, int n_in,
                              void* d_out, int out_size) {
    const float* x     = (const float*)d_in[0];
    const float* freq  = (const float*)d_in[1];
    const float* alpha = (const float*)d_in[2];
    const float* gate  = (const float*)d_in[3];
    const float* ln_g  = (const float*)d_in[4];
    const float* ln_b  = (const float*)d_in[5];
    const float* w_loc = (const float*)d_in[6];
    const float* b_loc = (const float*)d_in[7];
    float* out = (float*)d_out;

    static bool attr_done = false;
    if (!attr_done) {
        cudaFuncSetAttribute(k_mma, cudaFuncAttributeMaxDynamicSharedMemorySize, SMEM_TOTAL);
        attr_done = true;
    }

    k_prep1<<<512, 256>>>(freq, w_loc);
    k_thr<<<512, 256>>>(freq, alpha, gate);
    k_lnspec<<<512, 256>>>(x, ln_g, ln_b);
    k_mma<<<dim3(WID / TN, NTOK / TM), 256, SMEM_TOTAL>>>(b_loc, out);
}

// round 11
// speedup vs baseline: 3.1187x; 1.1635x over previous
#include <cuda_runtime.h>
#include <cuda_fp16.h>
#include <cstdint>
#include <math.h>

#define NTOK 4096
#define WID  512
#define FTOT 1024
#define SPECTRAL_SCALE 0.8f
#define ES_BETA 6.0f
#define TAU 0.001f
#define RHO 0.25f
#define LN_EPS 1e-5f
#define EPS_RMS 1e-8f

// ----- GEMM tiling -----
#define TM 128
#define TN 64
#define KC 128            // fp16 K elems per outer chunk
#define NKCH 4            // 512 / 128
#define ROWB 272          // padded row bytes: 136 halves (4-bank stride, conflict-free)
#define ATB (128 * ROWB)            // A tile bytes = 34816
#define WTB (64 * ROWB)             // W tile bytes = 17408
#define OFF_A  0
#define OFF_W  ATB
#define STGB (ATB + WTB)            // 52224
#define SMEM_TOTAL (2 * STGB)       // 104448 (double buffer) -> 2 CTAs/SM

// Scratch (no cudaMalloc allowed)
__device__ __half g_ah[NTOK * WID];
__device__ __half g_wh[WID * WID];
__device__ float g_spec[NTOK * WID];
__device__ float g_fnz[WID * FTOT];
__device__ float g_tnz[WID * FTOT];
__device__ int   g_cnt[WID];
__device__ float g_blockmax[512];

// ============================ PTX helpers ============================
__device__ __forceinline__ uint32_t smem_u32(const void* p) {
    uint32_t a;
    asm("{ .reg .u64 t; cvta.to.shared.u64 t, %1; cvt.u32.u64 %0, t; }" : "=r"(a) : "l"(p));
    return a;
}
__device__ __forceinline__ void cp_async16(uint32_t saddr, const void* gaddr) {
    asm volatile("cp.async.cg.shared.global [%0], [%1], 16;" :: "r"(saddr), "l"(gaddr));
}
#define CP_COMMIT() asm volatile("cp.async.commit_group;" ::: "memory")

__device__ __forceinline__ void ldsm_x4(uint32_t* r, uint32_t a) {
    asm volatile("ldmatrix.sync.aligned.m8n8.x4.shared.b16 {%0,%1,%2,%3}, [%4];"
                 : "=r"(r[0]), "=r"(r[1]), "=r"(r[2]), "=r"(r[3]) : "r"(a));
}
__device__ __forceinline__ void mma16816(float* d, const uint32_t* a, uint32_t b0, uint32_t b1) {
    asm volatile(
        "mma.sync.aligned.m16n8k16.row.col.f32.f16.f16.f32 "
        "{%0,%1,%2,%3}, {%4,%5,%6,%7}, {%8,%9}, {%0,%1,%2,%3};"
        : "+f"(d[0]), "+f"(d[1]), "+f"(d[2]), "+f"(d[3])
        : "r"(a[0]), "r"(a[1]), "r"(a[2]), "r"(a[3]), "r"(b0), "r"(b1));
}

// ============================ P1: reset + blockmax + W fp16 ============================
__global__ void __launch_bounds__(256) k_prep1(const float* __restrict__ freq,
                                               const float* __restrict__ w) {
    int tid = threadIdx.x, bid = blockIdx.x;
    int gid = bid * 256 + tid;                   // 131072 threads

    if (gid < WID) g_cnt[gid] = 0;

    {
        float2 wv = *(const float2*)(w + (size_t)gid * 2);
        __half2 hp = __halves2half2(__float2half(wv.x), __float2half(wv.y));
        *(uint32_t*)&g_wh[(size_t)gid * 2] = *(uint32_t*)&hp;
    }

    float4 f = *(const float4*)(freq + (size_t)gid * 4);
    float m = fmaxf(fmaxf(fabsf(f.x), fabsf(f.y)), fmaxf(fabsf(f.z), fabsf(f.w)))
              * SPECTRAL_SCALE;
    #pragma unroll
    for (int o = 16; o; o >>= 1) m = fmaxf(m, __shfl_xor_sync(0xffffffffu, m, o));
    __shared__ float s[8];
    int lane = tid & 31, wd = tid >> 5;
    if (lane == 0) s[wd] = m;
    __syncthreads();
    if (tid == 0) {
        float bm = s[0];
        #pragma unroll
        for (int i = 1; i < 8; ++i) bm = fmaxf(bm, s[i]);
        g_blockmax[bid] = bm;
    }
}

// ============================ P2: threshold -> compact lists ============================
__global__ void __launch_bounds__(256) k_thr(const float* __restrict__ freq,
                                             const float* __restrict__ alpha,
                                             const float* __restrict__ gate) {
    __shared__ float s[8];
    int tid = threadIdx.x;
    float m = fmaxf(g_blockmax[tid], g_blockmax[tid + 256]);
    #pragma unroll
    for (int o = 16; o; o >>= 1) m = fmaxf(m, __shfl_xor_sync(0xffffffffu, m, o));
    int lane = tid & 31, wd = tid >> 5;
    if (lane == 0) s[wd] = m;
    __syncthreads();
    float denom = s[0];
    #pragma unroll
    for (int i = 1; i < 8; ++i) denom = fmaxf(denom, s[i]);

    int base = (blockIdx.x * 256 + tid) * 4;
    float4 fv = *(const float4*)(freq + base);
    float4 av = *(const float4*)(alpha + base);
    float4 gv = *(const float4*)(gate + base);
    const float* fp = &fv.x;
    const float* ap = &av.x;
    const float* gp = &gv.x;
    #pragma unroll
    for (int u = 0; u < 4; ++u) {
        int i = base + u;
        float f = fp[u] * SPECTRAL_SCALE;
        float win;
        if (denom < 1e-8f) win = 1.f;
        else { float r = f / denom; win = expf(-ES_BETA * r * r); }
        float raw = ap[u] * gp[u];
        float mag = fabsf(raw) - TAU;
        if (mag > 0.f) {
            float t = copysignf(mag, raw) * win;
            if (t != 0.f) {
                int wdx = i & (WID - 1);
                int pos = atomicAdd(&g_cnt[wdx], 1);
                g_fnz[wdx * FTOT + pos] = f;
                g_tnz[wdx * FTOT + pos] = t;
            }
        }
    }
}

// ============================ P3: LayerNorm + spectral (warp per row) ============================
__global__ void __launch_bounds__(256) k_lnspec(const float* __restrict__ x,
                                                const float* __restrict__ gamma,
                                                const float* __restrict__ beta) {
    int lane = threadIdx.x & 31;
    int row = blockIdx.x * 8 + (threadIdx.x >> 5);
    const float4* xr = (const float4*)(x + (size_t)row * WID);
    float4 v[4];
    float s = 0.f, q = 0.f;
    #pragma unroll
    for (int i = 0; i < 4; ++i) {
        v[i] = xr[lane + 32 * i];
        s += v[i].x + v[i].y + v[i].z + v[i].w;
        q += v[i].x * v[i].x + v[i].y * v[i].y + v[i].z * v[i].z + v[i].w * v[i].w;
    }
    #pragma unroll
    for (int o = 16; o; o >>= 1) {
        s += __shfl_xor_sync(0xffffffffu, s, o);
        q += __shfl_xor_sync(0xffffffffu, q, o);
    }
    float mu = s * (1.f / WID);
    float inv = rsqrtf(q * (1.f / WID) - mu * mu + LN_EPS);

    float xn[16];
    #pragma unroll
    for (int i = 0; i < 4; ++i) {
        int cb = (lane + 32 * i) * 4;
        float4 g = ((const float4*)gamma)[lane + 32 * i];
        float4 b = ((const float4*)beta)[lane + 32 * i];
        float o0 = (v[i].x - mu) * inv * g.x + b.x;
        float o1 = (v[i].y - mu) * inv * g.y + b.y;
        float o2 = (v[i].z - mu) * inv * g.z + b.z;
        float o3 = (v[i].w - mu) * inv * g.w + b.w;
        xn[i * 4 + 0] = o0; xn[i * 4 + 1] = o1; xn[i * 4 + 2] = o2; xn[i * 4 + 3] = o3;
        __half2 hp0 = __halves2half2(__float2half(o0), __float2half(o1));
        __half2 hp1 = __halves2half2(__float2half(o2), __float2half(o3));
        *(uint2*)&g_ah[(size_t)row * WID + cb] =
            make_uint2(*(uint32_t*)&hp0, *(uint32_t*)&hp1);
    }

    float sv[16];
    float qq = 0.f;
    #pragma unroll
    for (int i = 0; i < 4; ++i) {
        #pragma unroll
        for (int u = 0; u < 4; ++u) {
            int wdx = (lane + 32 * i) * 4 + u;
            int cnt = g_cnt[wdx];
            const float* fp = g_fnz + wdx * FTOT;
            const float* tp = g_tnz + wdx * FTOT;
            float acc = 0.f;
            float xv = xn[i * 4 + u];
            for (int j = 0; j < cnt; ++j)
                acc += __sinf(xv * fp[j]) * tp[j];
            sv[i * 4 + u] = acc;
            qq += acc * acc;
        }
    }
    #pragma unroll
    for (int o = 16; o; o >>= 1) qq += __shfl_xor_sync(0xffffffffu, qq, o);
    float rinv = RHO * rsqrtf(qq * (1.f / WID) + EPS_RMS);
    #pragma unroll
    for (int i = 0; i < 4; ++i) {
        int cb = (lane + 32 * i) * 4;
        float4 o;
        o.x = sv[i * 4 + 0] * rinv; o.y = sv[i * 4 + 1] * rinv;
        o.z = sv[i * 4 + 2] * rinv; o.w = sv[i * 4 + 3] * rinv;
        *(float4*)(g_spec + (size_t)row * WID + cb) = o;
    }
}

// ============================ P4: HMMA GEMM (fp16 1-pass, KC=128, 2 CTAs/SM) ============================
__global__ void __launch_bounds__(256, 2)
k_mma(const float* __restrict__ bias, float* __restrict__ out) {
    extern __shared__ char smem[];
    uint32_t sb = smem_u32(smem);
    int tid = threadIdx.x;
    int wid = tid >> 5, lane = tid & 31;
    int warp_m = wid & 3;        // 4 warps over M (32 rows each)
    int warp_n = wid >> 2;       // 2 warps over N (32 cols each)

    int bm = blockIdx.y * TM;
    int bn = blockIdx.x * TN;

    float acc[2][4][4];
    #pragma unroll
    for (int i = 0; i < 2; ++i)
        #pragma unroll
        for (int j = 0; j < 4; ++j)
            #pragma unroll
            for (int k = 0; k < 4; ++k) acc[i][j][k] = 0.f;

    auto load_iter = [&](int k0, int stg) {
        int kcol = k0 * KC;
        uint32_t base = sb + stg * STGB;
        // A tile: 128 rows x 16 sixteen-byte cols = 2048 slots, 8 per thread
        #pragma unroll
        for (int it = 0; it < 8; ++it) {
            int idx = it * 256 + tid;
            int row = idx >> 4;
            int c16 = idx & 15;
            uint32_t so = (uint32_t)(row * ROWB + c16 * 16);
            cp_async16(base + OFF_A + so, g_ah + (size_t)(bm + row) * WID + kcol + c16 * 8);
        }
        // W tile: 64 rows x 16 = 1024 slots, 4 per thread
        #pragma unroll
        for (int it = 0; it < 4; ++it) {
            int idx = it * 256 + tid;
            int row = idx >> 4;
            int c16 = idx & 15;
            uint32_t so = (uint32_t)(row * ROWB + c16 * 16);
            cp_async16(base + OFF_W + so, g_wh + (size_t)(bn + row) * WID + kcol + c16 * 8);
        }
        CP_COMMIT();
    };

    load_iter(0, 0);

    for (int c = 0; c < NKCH; ++c) {
        if (c + 1 < NKCH) load_iter(c + 1, (c + 1) & 1);
        if (c + 1 < NKCH) asm volatile("cp.async.wait_group 1;" ::: "memory");
        else              asm volatile("cp.async.wait_group 0;" ::: "memory");
        __syncthreads();

        uint32_t base = sb + (c & 1) * STGB;
        #pragma unroll
        for (int ks = 0; ks < 8; ++ks) {
            uint32_t a_row_off =
                (uint32_t)((warp_m * 32 + (lane & 15)) * ROWB + (ks * 16 + (lane >> 4) * 8) * 2);
            uint32_t af[2][4];
            #pragma unroll
            for (int mt = 0; mt < 2; ++mt)
                ldsm_x4(af[mt], base + OFF_A + a_row_off + (uint32_t)(mt * 16 * ROWB));
            uint32_t bf[2][4];
            #pragma unroll
            for (int bt = 0; bt < 2; ++bt) {
                int nrow = warp_n * 32 + bt * 16 + (lane & 7) + ((lane >> 4) << 3);
                uint32_t addr = base + OFF_W
                    + (uint32_t)(nrow * ROWB + (ks * 16 + ((lane >> 3) & 1) * 8) * 2);
                ldsm_x4(bf[bt], addr);
            }
            #pragma unroll
            for (int mt = 0; mt < 2; ++mt)
                #pragma unroll
                for (int nt = 0; nt < 4; ++nt) {
                    int bt = nt >> 1, bi = (nt & 1) * 2;
                    mma16816(acc[mt][nt], af[mt], bf[bt][bi], bf[bt][bi + 1]);
                }
        }
        __syncthreads();
    }

    // ---- epilogue: bias + exact GELU + spectral add ----
    #pragma unroll
    for (int mt = 0; mt < 2; ++mt) {
        int r0 = bm + warp_m * 32 + mt * 16 + (lane >> 2);
        #pragma unroll
        for (int nt = 0; nt < 4; ++nt) {
            int c0 = bn + warp_n * 32 + nt * 8 + (lane & 3) * 2;
            float b0 = bias[c0], b1 = bias[c0 + 1];
            #pragma unroll
            for (int h = 0; h < 2; ++h) {
                int r = r0 + h * 8;
                float v0 = acc[mt][nt][h * 2 + 0] + b0;
                float v1 = acc[mt][nt][h * 2 + 1] + b1;
                float g0 = 0.5f * v0 * (1.f + erff(v0 * 0.70710678118654752f));
                float g1 = 0.5f * v1 * (1.f + erff(v1 * 0.70710678118654752f));
                float2 sp = *(const float2*)(g_spec + (size_t)r * WID + c0);
                float2 o = make_float2(g0 + sp.x, g1 + sp.y);
                *(float2*)(out + (size_t)r * WID + c0) = o;
            }
        }
    }
}

// ============================ launch ============================
extern "C" void kernel_launch(void* const* d_in, const int* in_sizes, int n_in,
                              void* d_out, int out_size) {
    const float* x     = (const float*)d_in[0];
    const float* freq  = (const float*)d_in[1];
    const float* alpha = (const float*)d_in[2];
    const float* gate  = (const float*)d_in[3];
    const float* ln_g  = (const float*)d_in[4];
    const float* ln_b  = (const float*)d_in[5];
    const float* w_loc = (const float*)d_in[6];
    const float* b_loc = (const float*)d_in[7];
    float* out = (float*)d_out;

    static bool attr_done = false;
    if (!attr_done) {
        cudaFuncSetAttribute(k_mma, cudaFuncAttributeMaxDynamicSharedMemorySize, SMEM_TOTAL);
        attr_done = true;
    }

    k_prep1<<<512, 256>>>(freq, w_loc);
    k_thr<<<512, 256>>>(freq, alpha, gate);
    k_lnspec<<<512, 256>>>(x, ln_g, ln_b);
    k_mma<<<dim3(WID / TN, NTOK / TM), 256, SMEM_TOTAL>>>(b_loc, out);
}